// round 5
// baseline (speedup 1.0000x reference)
#include <cuda_runtime.h>
#include <math.h>

#define NN 50000
#define NE 800000
#define NG 1024
#define NP 16384
#define NC 16
#define INCH 64
#define EMB 128
#define HID 256
#define BUCKET_SLOTS ((NP / 32 + NC) * 32)   // 16896
#define REG_BLOCKS (NP / 32 + NC)            // 528
#define NPB 128                               // nodes per scan block
#define NBLK ((NN + NPB - 1) / NPB)           // 391

// ---------------- scratch (static device memory) ----------------
__device__ float g_dinv[NN];
__device__ int   g_icnt[NN];
__device__ int   g_rowptr[NN + 1];
__device__ int   g_cursor_node[NN];
__device__ int   g_bsum[512];
__device__ int   g_csr[NE];
__device__ float g_tmp64[NN * INCH];
__device__ float g_hws[NN * EMB];
__device__ float g_tmp[NN * EMB];
__device__ float g_gsum[NG * EMB];
__device__ float g_ge[NG * EMB];
__device__ int   g_bucket[BUCKET_SLOTS];

// ---------------- helpers ----------------
__device__ __forceinline__ void red_add_v4(float* addr, float4 v) {
    asm volatile("red.global.add.v4.f32 [%0], {%1, %2, %3, %4};"
                 :: "l"(addr), "f"(v.x), "f"(v.y), "f"(v.z), "f"(v.w)
                 : "memory");
}
__device__ __forceinline__ float4 f4add(float4 a, float4 b) {
    return make_float4(a.x + b.x, a.y + b.y, a.z + b.z, a.w + b.w);
}

// ---------------- degree histogram ----------------
__global__ void k_icnt(const int* __restrict__ ei) {
    int e = blockIdx.x * blockDim.x + threadIdx.x;
    if (e < NE) atomicAdd(&g_icnt[ei[NE + e]], 1);   // target degree
}

// ---------------- prefix scan (+ fused dinv) ----------------
__global__ void k_scan1() {
    __shared__ int sm[NPB];
    int i = blockIdx.x * NPB + threadIdx.x;
    int v = (i < NN) ? g_icnt[i] : 0;
    if (i < NN) g_dinv[i] = rsqrtf((float)(v + 1));   // +1 self-loop
    sm[threadIdx.x] = v;
    __syncthreads();
    for (int s = NPB / 2; s > 0; s >>= 1) {
        if (threadIdx.x < s) sm[threadIdx.x] += sm[threadIdx.x + s];
        __syncthreads();
    }
    if (threadIdx.x == 0) g_bsum[blockIdx.x] = sm[0];
}
__global__ void k_scan2() {
    __shared__ int sm[512];
    int t = threadIdx.x;
    int v = (t < NBLK) ? g_bsum[t] : 0;
    sm[t] = v;
    __syncthreads();
    for (int s = 1; s < 512; s <<= 1) {
        int a = (t >= s) ? sm[t - s] : 0;
        __syncthreads();
        sm[t] += a;
        __syncthreads();
    }
    if (t < NBLK) g_bsum[t] = sm[t] - v;
}
__global__ void k_scan3() {
    __shared__ int sm[NPB];
    int t = threadIdx.x;
    int i = blockIdx.x * NPB + t;
    int v = (i < NN) ? g_icnt[i] : 0;
    sm[t] = v;
    __syncthreads();
    for (int s = 1; s < NPB; s <<= 1) {
        int a = (t >= s) ? sm[t - s] : 0;
        __syncthreads();
        sm[t] += a;
        __syncthreads();
    }
    if (i < NN) {
        int p = g_bsum[blockIdx.x] + sm[t] - v;
        g_rowptr[i] = p;
        g_cursor_node[i] = p;
        if (i == NN - 1) g_rowptr[NN] = NE;
    }
}
__global__ void k_fill(const int* __restrict__ ei) {
    int e = blockIdx.x * blockDim.x + threadIdx.x;
    if (e < NE) {
        int c = ei[NE + e];
        int pos = atomicAdd(&g_cursor_node[c], 1);
        g_csr[pos] = ei[e];
    }
}

// ---------------- layer-1 gather (half-warp per node, 8-edge unroll) ----------------
__global__ void __launch_bounds__(256) k_gather64(const float* __restrict__ x) {
    int warp = (blockIdx.x * 256 + threadIdx.x) >> 5;
    int lane = threadIdx.x & 31;
    int half = lane >> 4, l = lane & 15;
    int node = warp * 2 + half;
    if (node >= NN) return;

    float4 acc = *(const float4*)&x[node * INCH + l * 4];
    float d = g_dinv[node];
    acc.x *= d; acc.y *= d; acc.z *= d; acc.w *= d;
    float4 acc2 = make_float4(0.f, 0.f, 0.f, 0.f);

    int e = g_rowptr[node], end = g_rowptr[node + 1];
    for (; e + 8 <= end; e += 8) {
        int s0 = g_csr[e],     s1 = g_csr[e + 1], s2 = g_csr[e + 2], s3 = g_csr[e + 3];
        int s4 = g_csr[e + 4], s5 = g_csr[e + 5], s6 = g_csr[e + 6], s7 = g_csr[e + 7];
        float4 a0 = *(const float4*)&x[s0 * INCH + l * 4];
        float4 a1 = *(const float4*)&x[s1 * INCH + l * 4];
        float4 a2 = *(const float4*)&x[s2 * INCH + l * 4];
        float4 a3 = *(const float4*)&x[s3 * INCH + l * 4];
        float4 a4 = *(const float4*)&x[s4 * INCH + l * 4];
        float4 a5 = *(const float4*)&x[s5 * INCH + l * 4];
        float4 a6 = *(const float4*)&x[s6 * INCH + l * 4];
        float4 a7 = *(const float4*)&x[s7 * INCH + l * 4];
        float d0 = g_dinv[s0], d1 = g_dinv[s1], d2 = g_dinv[s2], d3 = g_dinv[s3];
        float d4 = g_dinv[s4], d5 = g_dinv[s5], d6 = g_dinv[s6], d7 = g_dinv[s7];
        acc.x  = fmaf(d0, a0.x, fmaf(d1, a1.x, fmaf(d2, a2.x, fmaf(d3, a3.x, acc.x))));
        acc.y  = fmaf(d0, a0.y, fmaf(d1, a1.y, fmaf(d2, a2.y, fmaf(d3, a3.y, acc.y))));
        acc.z  = fmaf(d0, a0.z, fmaf(d1, a1.z, fmaf(d2, a2.z, fmaf(d3, a3.z, acc.z))));
        acc.w  = fmaf(d0, a0.w, fmaf(d1, a1.w, fmaf(d2, a2.w, fmaf(d3, a3.w, acc.w))));
        acc2.x = fmaf(d4, a4.x, fmaf(d5, a5.x, fmaf(d6, a6.x, fmaf(d7, a7.x, acc2.x))));
        acc2.y = fmaf(d4, a4.y, fmaf(d5, a5.y, fmaf(d6, a6.y, fmaf(d7, a7.y, acc2.y))));
        acc2.z = fmaf(d4, a4.z, fmaf(d5, a5.z, fmaf(d6, a6.z, fmaf(d7, a7.z, acc2.z))));
        acc2.w = fmaf(d4, a4.w, fmaf(d5, a5.w, fmaf(d6, a6.w, fmaf(d7, a7.w, acc2.w))));
    }
    for (; e < end; e++) {
        int s = g_csr[e];
        float4 a = *(const float4*)&x[s * INCH + l * 4];
        float ds = g_dinv[s];
        acc.x = fmaf(ds, a.x, acc.x);
        acc.y = fmaf(ds, a.y, acc.y);
        acc.z = fmaf(ds, a.z, acc.z);
        acc.w = fmaf(ds, a.w, acc.w);
    }
    acc = f4add(acc, acc2);
    *(float4*)&g_tmp64[node * INCH + l * 4] = acc;
}

// ---------------- layer-2 gather (warp per node, 8-edge unroll) ----------------
__global__ void __launch_bounds__(256) k_gather128() {
    int node = (blockIdx.x * 256 + threadIdx.x) >> 5;
    int lane = threadIdx.x & 31;
    if (node >= NN) return;

    float4 acc = *(const float4*)&g_hws[node * EMB + lane * 4];  // self (dinv-scaled)
    float4 acc2 = make_float4(0.f, 0.f, 0.f, 0.f);

    int e = g_rowptr[node], end = g_rowptr[node + 1];
    for (; e + 8 <= end; e += 8) {
        int s0 = g_csr[e],     s1 = g_csr[e + 1], s2 = g_csr[e + 2], s3 = g_csr[e + 3];
        int s4 = g_csr[e + 4], s5 = g_csr[e + 5], s6 = g_csr[e + 6], s7 = g_csr[e + 7];
        float4 a0 = *(const float4*)&g_hws[s0 * EMB + lane * 4];
        float4 a1 = *(const float4*)&g_hws[s1 * EMB + lane * 4];
        float4 a2 = *(const float4*)&g_hws[s2 * EMB + lane * 4];
        float4 a3 = *(const float4*)&g_hws[s3 * EMB + lane * 4];
        float4 a4 = *(const float4*)&g_hws[s4 * EMB + lane * 4];
        float4 a5 = *(const float4*)&g_hws[s5 * EMB + lane * 4];
        float4 a6 = *(const float4*)&g_hws[s6 * EMB + lane * 4];
        float4 a7 = *(const float4*)&g_hws[s7 * EMB + lane * 4];
        acc  = f4add(acc,  f4add(f4add(a0, a1), f4add(a2, a3)));
        acc2 = f4add(acc2, f4add(f4add(a4, a5), f4add(a6, a7)));
    }
    for (; e + 4 <= end; e += 4) {
        int s0 = g_csr[e], s1 = g_csr[e + 1], s2 = g_csr[e + 2], s3 = g_csr[e + 3];
        float4 a0 = *(const float4*)&g_hws[s0 * EMB + lane * 4];
        float4 a1 = *(const float4*)&g_hws[s1 * EMB + lane * 4];
        float4 a2 = *(const float4*)&g_hws[s2 * EMB + lane * 4];
        float4 a3 = *(const float4*)&g_hws[s3 * EMB + lane * 4];
        acc = f4add(acc, f4add(f4add(a0, a1), f4add(a2, a3)));
    }
    for (; e < end; e++) {
        int s = g_csr[e];
        acc = f4add(acc, *(const float4*)&g_hws[s * EMB + lane * 4]);
    }
    acc = f4add(acc, acc2);
    *(float4*)&g_tmp[node * EMB + lane * 4] = acc;
}

// ---------------- fused GCN GEMM ----------------
template <int K, bool POOL>
__global__ void __launch_bounds__(256) k_gcn(
    const float* __restrict__ Xin, const float* __restrict__ W,
    const float* __restrict__ bias, const int* __restrict__ batch)
{
    constexpr int BM = 64;
    extern __shared__ float sm[];
    float* sW = sm;                  // K * 128
    float* sX = sm + K * 128;        // BM * (K+1)

    int tid = threadIdx.x;
    for (int i = tid; i < K * 32; i += 256)
        ((float4*)sW)[i] = ((const float4*)W)[i];

    int row0 = blockIdx.x * BM;
    for (int i = tid; i < BM * (K / 4); i += 256) {
        int r = i / (K / 4);
        int k = (i % (K / 4)) * 4;
        int gr = row0 + r;
        float4 v = make_float4(0.f, 0.f, 0.f, 0.f);
        if (gr < NN) {
            v = *(const float4*)&Xin[gr * K + k];
            float d = g_dinv[gr];
            v.x *= d; v.y *= d; v.z *= d; v.w *= d;
        }
        float* dst = &sX[r * (K + 1) + k];
        dst[0] = v.x; dst[1] = v.y; dst[2] = v.z; dst[3] = v.w;
    }
    __syncthreads();

    int warp = tid >> 5, lane = tid & 31;
    int r0 = warp * 8;
    float acc[8][4];
#pragma unroll
    for (int rr = 0; rr < 8; rr++)
        acc[rr][0] = acc[rr][1] = acc[rr][2] = acc[rr][3] = 0.f;

#pragma unroll 2
    for (int k = 0; k < K; k++) {
        float4 w4 = *(const float4*)&sW[k * 128 + lane * 4];
#pragma unroll
        for (int rr = 0; rr < 8; rr++) {
            float xv = sX[(r0 + rr) * (K + 1) + k];
            acc[rr][0] = fmaf(xv, w4.x, acc[rr][0]);
            acc[rr][1] = fmaf(xv, w4.y, acc[rr][1]);
            acc[rr][2] = fmaf(xv, w4.z, acc[rr][2]);
            acc[rr][3] = fmaf(xv, w4.w, acc[rr][3]);
        }
    }

    float4 b4 = *(const float4*)&bias[lane * 4];
#pragma unroll
    for (int rr = 0; rr < 8; rr++) {
        int gr = row0 + r0 + rr;
        if (gr >= NN) break;
        float4 o;
        o.x = fmaxf(acc[rr][0] + b4.x, 0.f);
        o.y = fmaxf(acc[rr][1] + b4.y, 0.f);
        o.z = fmaxf(acc[rr][2] + b4.z, 0.f);
        o.w = fmaxf(acc[rr][3] + b4.w, 0.f);
        if (POOL) {
            red_add_v4(&g_gsum[batch[gr] * EMB + lane * 4], o);
        } else {
            float d = g_dinv[gr];
            o.x *= d; o.y *= d; o.z *= d; o.w *= d;
            *(float4*)&g_hws[gr * EMB + lane * 4] = o;
        }
    }
}

// ---------------- mean epilogue: warp per graph, counts via binary search ----------------
__global__ void __launch_bounds__(256) k_ge(const int* __restrict__ batch) {
    int w = (blockIdx.x * 256 + threadIdx.x) >> 5;
    int lane = threadIdx.x & 31;
    if (w >= NG) return;
    int cnt = 0;
    if (lane == 0) {
        int lo = 0, hi = NN;
        while (lo < hi) { int m = (lo + hi) >> 1; if (batch[m] < w) lo = m + 1; else hi = m; }
        int a = lo;
        hi = NN;
        while (lo < hi) { int m = (lo + hi) >> 1; if (batch[m] < w + 1) lo = m + 1; else hi = m; }
        cnt = lo - a;
    }
    cnt = __shfl_sync(0xffffffffu, cnt, 0);
    float inv = 1.0f / fmaxf((float)cnt, 1.0f);
    float4 v = *(const float4*)&g_gsum[w * EMB + lane * 4];
    v.x *= inv; v.y *= inv; v.z *= inv; v.w *= inv;
    *(float4*)&g_ge[w * EMB + lane * 4] = v;
}

// ---------------- fused bucketing: count + prefix + init + scatter (one block) ----------------
__global__ void __launch_bounds__(1024) k_bucket(const int* __restrict__ ecl) {
    __shared__ int s_cnt[NC];
    __shared__ int s_start[NC];
    __shared__ int s_cur[NC];
    int t = threadIdx.x;
    if (t < NC) s_cnt[t] = 0;
    __syncthreads();
    for (int p = t; p < NP; p += 1024) atomicAdd(&s_cnt[ecl[p]], 1);
    __syncthreads();
    if (t == 0) {
        int a = 0;
        for (int c = 0; c < NC; c++) {
            s_start[c] = a;
            a += ((s_cnt[c] + 31) / 32) * 32;
        }
    }
    __syncthreads();
    for (int i = t; i < BUCKET_SLOTS; i += 1024) g_bucket[i] = -1;
    if (t < NC) s_cur[t] = s_start[t];
    __syncthreads();
    for (int p = t; p < NP; p += 1024) {
        int c = ecl[p];
        int pos = atomicAdd(&s_cur[c], 1);
        g_bucket[pos] = p;
    }
}

// ---------------- per-cell-line regressor: 32 pairs per block ----------------
__global__ void __launch_bounds__(256) k_reg(
    const int* __restrict__ ddb, const int* __restrict__ ecl,
    const float* __restrict__ w1, const float* __restrict__ b1,
    const float* __restrict__ w2, const float* __restrict__ b2,
    float* __restrict__ out)
{
    __shared__ int   s_pid[32];
    __shared__ float s_pair[32][HID];

    int tid = threadIdx.x;
    int base = blockIdx.x * 32;
    if (tid < 32) s_pid[tid] = g_bucket[base + tid];
    __syncthreads();

    int c = -1;
    for (int s = 0; s < 32 && c < 0; s++) {
        int p = s_pid[s];
        if (p >= 0) c = ecl[p];
    }
    if (c < 0) return;

    for (int i = tid; i < 32 * HID; i += 256) {
        int s = i >> 8, j = i & 255;
        int p = s_pid[s];
        float v = 0.0f;
        if (p >= 0) {
            int q = (j < 128) ? ddb[p] : ddb[NP + p];
            v = g_ge[q * EMB + (j & 127)];
        }
        s_pair[s][j] = v;
    }
    __syncthreads();

    const float* W = w1 + c * (HID * HID);
    float bt = b1[c * HID + tid];
    float acc[32];
#pragma unroll
    for (int s = 0; s < 32; s++) acc[s] = bt;

#pragma unroll 2
    for (int e = 0; e < HID; e += 4) {
        float wa = __ldg(&W[(e + 0) * HID + tid]);
        float wb = __ldg(&W[(e + 1) * HID + tid]);
        float wc = __ldg(&W[(e + 2) * HID + tid]);
        float wd = __ldg(&W[(e + 3) * HID + tid]);
#pragma unroll
        for (int s = 0; s < 32; s++) {
            float4 pv = *(const float4*)&s_pair[s][e];
            acc[s] = fmaf(pv.x, wa, fmaf(pv.y, wb, fmaf(pv.z, wc, fmaf(pv.w, wd, acc[s]))));
        }
    }

    float w2v = w2[c * HID + tid];
    __syncthreads();
#pragma unroll
    for (int s = 0; s < 32; s++) s_pair[s][tid] = fmaxf(acc[s], 0.0f) * w2v;
    __syncthreads();

    int s = tid >> 3, g = tid & 7;
    const float* rowp = &s_pair[s][g * 32];
    float sum = 0.0f;
#pragma unroll
    for (int j = 0; j < 32; j++) sum += rowp[j];
    sum += __shfl_down_sync(0xffffffffu, sum, 4, 8);
    sum += __shfl_down_sync(0xffffffffu, sum, 2, 8);
    sum += __shfl_down_sync(0xffffffffu, sum, 1, 8);
    if (g == 0) {
        int p = s_pid[s];
        if (p >= 0) out[p] = sum + b2[c];
    }
}

// ---------------- host launch ----------------
extern "C" void kernel_launch(void* const* d_in, const int* in_sizes, int n_in,
                              void* d_out, int out_size)
{
    const float* x    = (const float*)d_in[0];
    const float* c1w  = (const float*)d_in[1];
    const float* c1b  = (const float*)d_in[2];
    const float* c2w  = (const float*)d_in[3];
    const float* c2b  = (const float*)d_in[4];
    const float* rw1  = (const float*)d_in[5];
    const float* rb1  = (const float*)d_in[6];
    const float* rw2  = (const float*)d_in[7];
    const float* rb2  = (const float*)d_in[8];
    const int*   ei   = (const int*)d_in[9];
    const int*   bat  = (const int*)d_in[10];
    const int*   ddb  = (const int*)d_in[11];
    const int*   ecl  = (const int*)d_in[12];
    float* out = (float*)d_out;

    static bool attr_done = false;
    if (!attr_done) {
        cudaFuncSetAttribute(k_gcn<64, false>,
                             cudaFuncAttributeMaxDynamicSharedMemorySize, 49408);
        cudaFuncSetAttribute(k_gcn<128, true>,
                             cudaFuncAttributeMaxDynamicSharedMemorySize, 98560);
        attr_done = true;
    }

    float* tmp64_ptr = nullptr;
    float* tmp_ptr = nullptr;
    void* icnt_ptr = nullptr;
    void* gsum_ptr = nullptr;
    cudaGetSymbolAddress((void**)&tmp64_ptr, g_tmp64);
    cudaGetSymbolAddress((void**)&tmp_ptr, g_tmp);
    cudaGetSymbolAddress(&icnt_ptr, g_icnt);
    cudaGetSymbolAddress(&gsum_ptr, g_gsum);

    const int T = 256;

    // zeroing via async memset (graph-capturable, no kernel-launch overhead)
    cudaMemsetAsync(icnt_ptr, 0, NN * sizeof(int), 0);
    cudaMemsetAsync(gsum_ptr, 0, NG * EMB * sizeof(float), 0);

    // degree histogram + dinv + CSR build
    k_icnt<<<(NE + T - 1) / T, T>>>(ei);
    k_scan1<<<NBLK, NPB>>>();
    k_scan2<<<1, 512>>>();
    k_scan3<<<NBLK, NPB>>>();
    k_fill<<<(NE + T - 1) / T, T>>>(ei);

    // layer 1: gather in 64-dim, then transform
    k_gather64<<<(NN / 2 + 7) / 8, T>>>(x);
    k_gcn<64, false><<<(NN + 63) / 64, T, 49408>>>(tmp64_ptr, c1w, c1b, nullptr);

    // layer 2: gather 128-dim, transform fused with pooling
    k_gather128<<<(NN + 7) / 8, T>>>();
    k_gcn<128, true><<<(NN + 63) / 64, T, 98560>>>(tmp_ptr, c2w, c2b, bat);
    k_ge<<<(NG * 32 + T - 1) / T, T>>>(bat);

    // bucket pairs by cell line (single fused kernel)
    k_bucket<<<1, 1024>>>(ecl);

    // regressor
    k_reg<<<REG_BLOCKS, T>>>(ddb, ecl, rw1, rb1, rw2, rb2, out);
}

// round 7
// speedup vs baseline: 1.3129x; 1.3129x over previous
#include <cuda_runtime.h>
#include <math.h>
#include <stdint.h>

#define NN 50000
#define NE 800000
#define NG 1024
#define NP 16384
#define NC 16
#define INCH 64
#define EMB 128
#define HID 256
#define BUCKET_SLOTS ((NP / 32 + NC) * 32)   // 16896
#define REG_BLOCKS (NP / 32 + NC)            // 528
#define NPB 128
#define NBLK ((NN + NPB - 1) / NPB)           // 391

// ---------------- scratch ----------------
__device__ float g_dinv[NN];
__device__ int   g_icnt[NN];
__device__ int   g_rowptr[NN + 1];
__device__ int   g_cursor_node[NN];
__device__ int   g_bsum[512];
__device__ int   g_csr[NE];
__device__ float g_hws[NN * EMB];
__device__ float g_gsum[NG * EMB];
__device__ float g_ge[NG * EMB];
__device__ int   g_bucket[BUCKET_SLOTS];

// ---------------- helpers ----------------
__device__ __forceinline__ void red_add_v4(float* addr, float4 v) {
    asm volatile("red.global.add.v4.f32 [%0], {%1, %2, %3, %4};"
                 :: "l"(addr), "f"(v.x), "f"(v.y), "f"(v.z), "f"(v.w)
                 : "memory");
}
__device__ __forceinline__ float4 f4add(float4 a, float4 b) {
    return make_float4(a.x + b.x, a.y + b.y, a.z + b.z, a.w + b.w);
}
__device__ __forceinline__ uint32_t cvt_tf32(float f) {
    uint32_t u;
    asm("cvt.rna.tf32.f32 %0, %1;" : "=r"(u) : "f"(f));
    return u;
}
__device__ __forceinline__ void mma_tf32(float* d, const uint32_t* a,
                                         uint32_t b0, uint32_t b1) {
    asm("mma.sync.aligned.m16n8k8.row.col.f32.tf32.tf32.f32 "
        "{%0,%1,%2,%3}, {%4,%5,%6,%7}, {%8,%9}, {%0,%1,%2,%3};"
        : "+f"(d[0]), "+f"(d[1]), "+f"(d[2]), "+f"(d[3])
        : "r"(a[0]), "r"(a[1]), "r"(a[2]), "r"(a[3]), "r"(b0), "r"(b1));
}

// ---------------- degree histogram ----------------
__global__ void k_icnt(const int* __restrict__ ei) {
    int e = blockIdx.x * blockDim.x + threadIdx.x;
    if (e < NE) atomicAdd(&g_icnt[ei[NE + e]], 1);
}

// ---------------- prefix scan (+ fused dinv) ----------------
__global__ void k_scan1() {
    __shared__ int sm[NPB];
    int i = blockIdx.x * NPB + threadIdx.x;
    int v = (i < NN) ? g_icnt[i] : 0;
    if (i < NN) g_dinv[i] = rsqrtf((float)(v + 1));
    sm[threadIdx.x] = v;
    __syncthreads();
    for (int s = NPB / 2; s > 0; s >>= 1) {
        if (threadIdx.x < s) sm[threadIdx.x] += sm[threadIdx.x + s];
        __syncthreads();
    }
    if (threadIdx.x == 0) g_bsum[blockIdx.x] = sm[0];
}
__global__ void k_scan2() {
    __shared__ int sm[512];
    int t = threadIdx.x;
    int v = (t < NBLK) ? g_bsum[t] : 0;
    sm[t] = v;
    __syncthreads();
    for (int s = 1; s < 512; s <<= 1) {
        int a = (t >= s) ? sm[t - s] : 0;
        __syncthreads();
        sm[t] += a;
        __syncthreads();
    }
    if (t < NBLK) g_bsum[t] = sm[t] - v;
}
__global__ void k_scan3() {
    __shared__ int sm[NPB];
    int t = threadIdx.x;
    int i = blockIdx.x * NPB + t;
    int v = (i < NN) ? g_icnt[i] : 0;
    sm[t] = v;
    __syncthreads();
    for (int s = 1; s < NPB; s <<= 1) {
        int a = (t >= s) ? sm[t - s] : 0;
        __syncthreads();
        sm[t] += a;
        __syncthreads();
    }
    if (i < NN) {
        int p = g_bsum[blockIdx.x] + sm[t] - v;
        g_rowptr[i] = p;
        g_cursor_node[i] = p;
        if (i == NN - 1) g_rowptr[NN] = NE;
    }
}
__global__ void k_fill(const int* __restrict__ ei) {
    int e = blockIdx.x * blockDim.x + threadIdx.x;
    if (e < NE) {
        int c = ei[NE + e];
        int pos = atomicAdd(&g_cursor_node[c], 1);
        g_csr[pos] = ei[e];
    }
}

// ---------------- fused gather + GCN GEMM, layer 1 (K=64) ----------------
__global__ void __launch_bounds__(256) k_gcn1(
    const float* __restrict__ x, const float* __restrict__ W,
    const float* __restrict__ bias)
{
    constexpr int K = 64, KP = 68, BM = 64;
    extern __shared__ float sm[];
    float* sW = sm;             // K*128 = 8192
    float* sX = sm + K * 128;   // BM*KP

    int tid = threadIdx.x;
    int warp = tid >> 5, lane = tid & 31;
    int row0 = blockIdx.x * BM;

    for (int i = tid; i < K * 32; i += 256)
        ((float4*)sW)[i] = ((const float4*)W)[i];

    // gather phase: 4 iterations of 2 nodes per warp (half-warp each)
    int half = lane >> 4, l = lane & 15;
    for (int it = 0; it < 4; it++) {
        int nl = warp * 8 + it * 2 + half;
        int node = row0 + nl;
        float4 acc = make_float4(0.f, 0.f, 0.f, 0.f);
        if (node < NN) {
            float dn = g_dinv[node];
            acc = *(const float4*)&x[node * INCH + l * 4];
            acc.x *= dn; acc.y *= dn; acc.z *= dn; acc.w *= dn;
            int e = g_rowptr[node], end = g_rowptr[node + 1];
            for (; e + 4 <= end; e += 4) {
                int s0 = g_csr[e], s1 = g_csr[e + 1], s2 = g_csr[e + 2], s3 = g_csr[e + 3];
                float4 a0 = *(const float4*)&x[s0 * INCH + l * 4];
                float4 a1 = *(const float4*)&x[s1 * INCH + l * 4];
                float4 a2 = *(const float4*)&x[s2 * INCH + l * 4];
                float4 a3 = *(const float4*)&x[s3 * INCH + l * 4];
                float d0 = g_dinv[s0], d1 = g_dinv[s1], d2 = g_dinv[s2], d3 = g_dinv[s3];
                acc.x = fmaf(d0, a0.x, fmaf(d1, a1.x, fmaf(d2, a2.x, fmaf(d3, a3.x, acc.x))));
                acc.y = fmaf(d0, a0.y, fmaf(d1, a1.y, fmaf(d2, a2.y, fmaf(d3, a3.y, acc.y))));
                acc.z = fmaf(d0, a0.z, fmaf(d1, a1.z, fmaf(d2, a2.z, fmaf(d3, a3.z, acc.z))));
                acc.w = fmaf(d0, a0.w, fmaf(d1, a1.w, fmaf(d2, a2.w, fmaf(d3, a3.w, acc.w))));
            }
            for (; e < end; e++) {
                int s = g_csr[e];
                float4 a = *(const float4*)&x[s * INCH + l * 4];
                float ds = g_dinv[s];
                acc.x = fmaf(ds, a.x, acc.x);
                acc.y = fmaf(ds, a.y, acc.y);
                acc.z = fmaf(ds, a.z, acc.z);
                acc.w = fmaf(ds, a.w, acc.w);
            }
            // left norm (reuse dn)
            acc.x *= dn; acc.y *= dn; acc.z *= dn; acc.w *= dn;
        }
        *(float4*)&sX[nl * KP + l * 4] = acc;
    }
    __syncthreads();

    // GEMM phase: 8 rows x 4 cols per thread
    int r0 = warp * 8;
    float acc[8][4];
#pragma unroll
    for (int rr = 0; rr < 8; rr++)
        acc[rr][0] = acc[rr][1] = acc[rr][2] = acc[rr][3] = 0.f;
#pragma unroll 2
    for (int k = 0; k < K; k++) {
        float4 w4 = *(const float4*)&sW[k * 128 + lane * 4];
#pragma unroll
        for (int rr = 0; rr < 8; rr++) {
            float xv = sX[(r0 + rr) * KP + k];
            acc[rr][0] = fmaf(xv, w4.x, acc[rr][0]);
            acc[rr][1] = fmaf(xv, w4.y, acc[rr][1]);
            acc[rr][2] = fmaf(xv, w4.z, acc[rr][2]);
            acc[rr][3] = fmaf(xv, w4.w, acc[rr][3]);
        }
    }
    float4 b4 = *(const float4*)&bias[lane * 4];
#pragma unroll
    for (int rr = 0; rr < 8; rr++) {
        int gr = row0 + r0 + rr;
        if (gr >= NN) break;
        float d = g_dinv[gr];
        float4 o;
        o.x = fmaxf(acc[rr][0] + b4.x, 0.f) * d;
        o.y = fmaxf(acc[rr][1] + b4.y, 0.f) * d;
        o.z = fmaxf(acc[rr][2] + b4.z, 0.f) * d;
        o.w = fmaxf(acc[rr][3] + b4.w, 0.f) * d;
        *(float4*)&g_hws[gr * EMB + lane * 4] = o;
    }
}

// ---------------- fused gather + GCN GEMM + pool, layer 2 (K=128) ----------------
__global__ void __launch_bounds__(256) k_gcn2(
    const float* __restrict__ W, const float* __restrict__ bias,
    const int* __restrict__ batch)
{
    constexpr int K = 128, KP = 132, BM = 64;
    extern __shared__ float sm[];
    float* sW = sm;              // 128*128
    float* sX = sm + K * 128;    // BM*KP

    int tid = threadIdx.x;
    int warp = tid >> 5, lane = tid & 31;
    int row0 = blockIdx.x * BM;

    for (int i = tid; i < K * 32; i += 256)
        ((float4*)sW)[i] = ((const float4*)W)[i];

    // gather phase: warp per node, 8 nodes per warp
    for (int it = 0; it < 8; it++) {
        int nl = warp * 8 + it;
        int node = row0 + nl;
        float4 acc = make_float4(0.f, 0.f, 0.f, 0.f);
        if (node < NN) {
            acc = *(const float4*)&g_hws[node * EMB + lane * 4];  // self
            int e = g_rowptr[node], end = g_rowptr[node + 1];
            for (; e + 4 <= end; e += 4) {
                int s0 = g_csr[e], s1 = g_csr[e + 1], s2 = g_csr[e + 2], s3 = g_csr[e + 3];
                float4 a0 = *(const float4*)&g_hws[s0 * EMB + lane * 4];
                float4 a1 = *(const float4*)&g_hws[s1 * EMB + lane * 4];
                float4 a2 = *(const float4*)&g_hws[s2 * EMB + lane * 4];
                float4 a3 = *(const float4*)&g_hws[s3 * EMB + lane * 4];
                acc = f4add(acc, f4add(f4add(a0, a1), f4add(a2, a3)));
            }
            for (; e < end; e++) {
                int s = g_csr[e];
                acc = f4add(acc, *(const float4*)&g_hws[s * EMB + lane * 4]);
            }
            float dn = g_dinv[node];
            acc.x *= dn; acc.y *= dn; acc.z *= dn; acc.w *= dn;
        }
        *(float4*)&sX[nl * KP + lane * 4] = acc;
    }
    __syncthreads();

    int r0 = warp * 8;
    float acc[8][4];
#pragma unroll
    for (int rr = 0; rr < 8; rr++)
        acc[rr][0] = acc[rr][1] = acc[rr][2] = acc[rr][3] = 0.f;
#pragma unroll 2
    for (int k = 0; k < K; k++) {
        float4 w4 = *(const float4*)&sW[k * 128 + lane * 4];
#pragma unroll
        for (int rr = 0; rr < 8; rr++) {
            float xv = sX[(r0 + rr) * KP + k];
            acc[rr][0] = fmaf(xv, w4.x, acc[rr][0]);
            acc[rr][1] = fmaf(xv, w4.y, acc[rr][1]);
            acc[rr][2] = fmaf(xv, w4.z, acc[rr][2]);
            acc[rr][3] = fmaf(xv, w4.w, acc[rr][3]);
        }
    }
    float4 b4 = *(const float4*)&bias[lane * 4];
#pragma unroll
    for (int rr = 0; rr < 8; rr++) {
        int gr = row0 + r0 + rr;
        if (gr >= NN) break;
        float4 o;
        o.x = fmaxf(acc[rr][0] + b4.x, 0.f);
        o.y = fmaxf(acc[rr][1] + b4.y, 0.f);
        o.z = fmaxf(acc[rr][2] + b4.z, 0.f);
        o.w = fmaxf(acc[rr][3] + b4.w, 0.f);
        red_add_v4(&g_gsum[batch[gr] * EMB + lane * 4], o);
    }
}

// ---------------- mean epilogue ----------------
__global__ void __launch_bounds__(256) k_ge(const int* __restrict__ batch) {
    int w = (blockIdx.x * 256 + threadIdx.x) >> 5;
    int lane = threadIdx.x & 31;
    if (w >= NG) return;
    int cnt = 0;
    if (lane == 0) {
        int lo = 0, hi = NN;
        while (lo < hi) { int m = (lo + hi) >> 1; if (batch[m] < w) lo = m + 1; else hi = m; }
        int a = lo;
        hi = NN;
        while (lo < hi) { int m = (lo + hi) >> 1; if (batch[m] < w + 1) lo = m + 1; else hi = m; }
        cnt = lo - a;
    }
    cnt = __shfl_sync(0xffffffffu, cnt, 0);
    float inv = 1.0f / fmaxf((float)cnt, 1.0f);
    float4 v = *(const float4*)&g_gsum[w * EMB + lane * 4];
    v.x *= inv; v.y *= inv; v.z *= inv; v.w *= inv;
    *(float4*)&g_ge[w * EMB + lane * 4] = v;
}

// ---------------- fused bucketing ----------------
__global__ void __launch_bounds__(1024) k_bucket(const int* __restrict__ ecl) {
    __shared__ int s_cnt[NC];
    __shared__ int s_start[NC];
    __shared__ int s_cur[NC];
    int t = threadIdx.x;
    if (t < NC) s_cnt[t] = 0;
    __syncthreads();
    for (int p = t; p < NP; p += 1024) atomicAdd(&s_cnt[ecl[p]], 1);
    __syncthreads();
    if (t == 0) {
        int a = 0;
        for (int c = 0; c < NC; c++) {
            s_start[c] = a;
            a += ((s_cnt[c] + 31) / 32) * 32;
        }
    }
    __syncthreads();
    for (int i = t; i < BUCKET_SLOTS; i += 1024) g_bucket[i] = -1;
    if (t < NC) s_cur[t] = s_start[t];
    __syncthreads();
    for (int p = t; p < NP; p += 1024) {
        int c = ecl[p];
        int pos = atomicAdd(&s_cur[c], 1);
        g_bucket[pos] = p;
    }
}

// ---------------- tf32 tensor-core regressor: 32 pairs per block ----------------
__global__ void __launch_bounds__(256) k_reg(
    const int* __restrict__ ddb, const int* __restrict__ ecl,
    const float* __restrict__ w1, const float* __restrict__ b1,
    const float* __restrict__ w2, const float* __restrict__ b2,
    float* __restrict__ out)
{
    __shared__ int      s_pid[32];
    __shared__ uint32_t s_pairU[32 * 268];   // tf32 bits, stride 268
    __shared__ float    s_b1[HID];
    __shared__ float    s_w2[HID];
    __shared__ float    s_out[32];

    int tid = threadIdx.x;
    int warp = tid >> 5, lane = tid & 31;
    int base = blockIdx.x * 32;
    if (tid < 32) { s_pid[tid] = g_bucket[base + tid]; s_out[tid] = 0.f; }
    __syncthreads();

    int c = -1;
    for (int s = 0; s < 32 && c < 0; s++) {
        int p = s_pid[s];
        if (p >= 0) c = ecl[p];
    }
    if (c < 0) return;   // all-padding block (uniform)

    s_b1[tid] = b1[c * HID + tid];
    s_w2[tid] = w2[c * HID + tid];

    // gather pair tile (tf32-rounded): [32 pairs][256] = concat(ge[q0], ge[q1])
    for (int i = tid; i < 32 * HID; i += 256) {
        int s = i >> 8, j = i & 255;
        int p = s_pid[s];
        float v = 0.0f;
        if (p >= 0) {
            int q = (j < 128) ? ddb[p] : ddb[NP + p];
            v = g_ge[q * EMB + (j & 127)];
        }
        s_pairU[s * 268 + j] = cvt_tf32(v);
    }
    __syncthreads();

    const float* Wc = w1 + c * (HID * HID);
    int n0 = warp * 32;                 // this warp's 32-column slice
    int ra = lane >> 2, ca = lane & 3;  // groupID / threadID-in-group

    float d[2][4][4];
#pragma unroll
    for (int mt = 0; mt < 2; mt++)
#pragma unroll
        for (int nt = 0; nt < 4; nt++)
            d[mt][nt][0] = d[mt][nt][1] = d[mt][nt][2] = d[mt][nt][3] = 0.f;

    for (int k0 = 0; k0 < HID; k0 += 8) {
        const uint32_t* pr = &s_pairU[ra * 268 + k0 + ca];
        uint32_t A[2][4];
        A[0][0] = pr[0];
        A[0][1] = pr[8 * 268];
        A[0][2] = pr[4];
        A[0][3] = pr[8 * 268 + 4];
        A[1][0] = pr[16 * 268];
        A[1][1] = pr[24 * 268];
        A[1][2] = pr[16 * 268 + 4];
        A[1][3] = pr[24 * 268 + 4];
        const float* wp0 = Wc + (k0 + ca) * HID + n0 + ra;
        const float* wp1 = wp0 + 4 * HID;
#pragma unroll
        for (int nt = 0; nt < 4; nt++) {
            uint32_t b0 = cvt_tf32(__ldg(wp0 + nt * 8));
            uint32_t b1v = cvt_tf32(__ldg(wp1 + nt * 8));
            mma_tf32(d[0][nt], A[0], b0, b1v);
            mma_tf32(d[1][nt], A[1], b0, b1v);
        }
    }

    // epilogue: bias + relu + w2 weight + row reduction
    float rowsum[2][2] = {{0.f, 0.f}, {0.f, 0.f}};
#pragma unroll
    for (int mt = 0; mt < 2; mt++) {
#pragma unroll
        for (int nt = 0; nt < 4; nt++) {
            int colb = n0 + nt * 8 + 2 * ca;
            float b1a = s_b1[colb],     w2a = s_w2[colb];
            float b1b = s_b1[colb + 1], w2b = s_w2[colb + 1];
            rowsum[mt][0] += fmaxf(d[mt][nt][0] + b1a, 0.f) * w2a
                           + fmaxf(d[mt][nt][1] + b1b, 0.f) * w2b;
            rowsum[mt][1] += fmaxf(d[mt][nt][2] + b1a, 0.f) * w2a
                           + fmaxf(d[mt][nt][3] + b1b, 0.f) * w2b;
        }
    }
#pragma unroll
    for (int mt = 0; mt < 2; mt++)
#pragma unroll
        for (int hi = 0; hi < 2; hi++) {
            float v = rowsum[mt][hi];
            v += __shfl_xor_sync(0xffffffffu, v, 1);
            v += __shfl_xor_sync(0xffffffffu, v, 2);
            if (ca == 0) atomicAdd(&s_out[mt * 16 + hi * 8 + ra], v);
        }
    __syncthreads();

    if (tid < 32) {
        int p = s_pid[tid];
        if (p >= 0) out[p] = s_out[tid] + b2[c];
    }
}

// ---------------- host launch ----------------
extern "C" void kernel_launch(void* const* d_in, const int* in_sizes, int n_in,
                              void* d_out, int out_size)
{
    const float* x    = (const float*)d_in[0];
    const float* c1w  = (const float*)d_in[1];
    const float* c1b  = (const float*)d_in[2];
    const float* c2w  = (const float*)d_in[3];
    const float* c2b  = (const float*)d_in[4];
    const float* rw1  = (const float*)d_in[5];
    const float* rb1  = (const float*)d_in[6];
    const float* rw2  = (const float*)d_in[7];
    const float* rb2  = (const float*)d_in[8];
    const int*   ei   = (const int*)d_in[9];
    const int*   bat  = (const int*)d_in[10];
    const int*   ddb  = (const int*)d_in[11];
    const int*   ecl  = (const int*)d_in[12];
    float* out = (float*)d_out;

    static bool attr_done = false;
    if (!attr_done) {
        cudaFuncSetAttribute(k_gcn1, cudaFuncAttributeMaxDynamicSharedMemorySize, 50176);
        cudaFuncSetAttribute(k_gcn2, cudaFuncAttributeMaxDynamicSharedMemorySize, 99328);
        attr_done = true;
    }

    void* icnt_ptr = nullptr;
    void* gsum_ptr = nullptr;
    cudaGetSymbolAddress(&icnt_ptr, g_icnt);
    cudaGetSymbolAddress(&gsum_ptr, g_gsum);

    const int T = 256;

    cudaMemsetAsync(icnt_ptr, 0, NN * sizeof(int), 0);
    cudaMemsetAsync(gsum_ptr, 0, NG * EMB * sizeof(float), 0);

    // degree histogram + dinv + CSR build
    k_icnt<<<(NE + T - 1) / T, T>>>(ei);
    k_scan1<<<NBLK, NPB>>>();
    k_scan2<<<1, 512>>>();
    k_scan3<<<NBLK, NPB>>>();
    k_fill<<<(NE + T - 1) / T, T>>>(ei);

    // layer 1: fused gather(64) + GEMM
    k_gcn1<<<(NN + 63) / 64, T, 50176>>>(x, c1w, c1b);

    // layer 2: fused gather(128) + GEMM + pooling
    k_gcn2<<<(NN + 63) / 64, T, 99328>>>(c2w, c2b, bat);
    k_ge<<<(NG * 32 + T - 1) / T, T>>>(bat);

    // bucketing + regressor (tf32 tensor cores)
    k_bucket<<<1, 1024>>>(ecl);
    k_reg<<<REG_BLOCKS, T>>>(ddb, ecl, rw1, rb1, rw2, rb2, out);
}

// round 8
// speedup vs baseline: 1.3957x; 1.0631x over previous
#include <cuda_runtime.h>
#include <math.h>
#include <stdint.h>

#define NN 50000
#define NE 800000
#define NG 1024
#define NP 16384
#define NC 16
#define INCH 64
#define EMB 128
#define HID 256
#define BUCKET_SLOTS ((NP / 32 + NC) * 32)   // 16896
#define REG_BLOCKS (NP / 32 + NC)            // 528
#define NPB 128
#define NBLK ((NN + NPB - 1) / NPB)           // 391

// ---------------- scratch ----------------
__device__ float g_dinv[NN];
__device__ int   g_icnt[NN];
__device__ int   g_rowptr[NN + 1];
__device__ int   g_cursor_node[NN];
__device__ int   g_bsum[512];
__device__ int   g_csr[NE];
__device__ float g_hws[NN * EMB];
__device__ float g_gsum[NG * EMB];
__device__ float g_ge[NG * EMB];
__device__ int   g_bucket[BUCKET_SLOTS];

// ---------------- helpers ----------------
__device__ __forceinline__ void red_add_v2(float* addr, float a, float b) {
    asm volatile("red.global.add.v2.f32 [%0], {%1, %2};"
                 :: "l"(addr), "f"(a), "f"(b) : "memory");
}
__device__ __forceinline__ float4 f4add(float4 a, float4 b) {
    return make_float4(a.x + b.x, a.y + b.y, a.z + b.z, a.w + b.w);
}
__device__ __forceinline__ uint32_t cvt_tf32(float f) {
    uint32_t u;
    asm("cvt.rna.tf32.f32 %0, %1;" : "=r"(u) : "f"(f));
    return u;
}
__device__ __forceinline__ void mma_tf32(float* d, const uint32_t* a,
                                         uint32_t b0, uint32_t b1) {
    asm("mma.sync.aligned.m16n8k8.row.col.f32.tf32.tf32.f32 "
        "{%0,%1,%2,%3}, {%4,%5,%6,%7}, {%8,%9}, {%0,%1,%2,%3};"
        : "+f"(d[0]), "+f"(d[1]), "+f"(d[2]), "+f"(d[3])
        : "r"(a[0]), "r"(a[1]), "r"(a[2]), "r"(a[3]), "r"(b0), "r"(b1));
}

// ---------------- degree histogram (4 edges per thread) ----------------
__global__ void k_icnt(const int* __restrict__ ei) {
    int i = blockIdx.x * blockDim.x + threadIdx.x;
    if (i < NE / 4) {
        int4 t = ((const int4*)(ei + NE))[i];
        atomicAdd(&g_icnt[t.x], 1);
        atomicAdd(&g_icnt[t.y], 1);
        atomicAdd(&g_icnt[t.z], 1);
        atomicAdd(&g_icnt[t.w], 1);
    }
}

// ---------------- prefix scan (+ fused dinv) ----------------
__global__ void k_scan1() {
    __shared__ int sm[NPB];
    int i = blockIdx.x * NPB + threadIdx.x;
    int v = (i < NN) ? g_icnt[i] : 0;
    if (i < NN) g_dinv[i] = rsqrtf((float)(v + 1));
    sm[threadIdx.x] = v;
    __syncthreads();
    for (int s = NPB / 2; s > 0; s >>= 1) {
        if (threadIdx.x < s) sm[threadIdx.x] += sm[threadIdx.x + s];
        __syncthreads();
    }
    if (threadIdx.x == 0) g_bsum[blockIdx.x] = sm[0];
}
__global__ void k_scan2() {
    __shared__ int sm[512];
    int t = threadIdx.x;
    int v = (t < NBLK) ? g_bsum[t] : 0;
    sm[t] = v;
    __syncthreads();
    for (int s = 1; s < 512; s <<= 1) {
        int a = (t >= s) ? sm[t - s] : 0;
        __syncthreads();
        sm[t] += a;
        __syncthreads();
    }
    if (t < NBLK) g_bsum[t] = sm[t] - v;
}
__global__ void k_scan3() {
    __shared__ int sm[NPB];
    int t = threadIdx.x;
    int i = blockIdx.x * NPB + t;
    int v = (i < NN) ? g_icnt[i] : 0;
    sm[t] = v;
    __syncthreads();
    for (int s = 1; s < NPB; s <<= 1) {
        int a = (t >= s) ? sm[t - s] : 0;
        __syncthreads();
        sm[t] += a;
        __syncthreads();
    }
    if (i < NN) {
        int p = g_bsum[blockIdx.x] + sm[t] - v;
        g_rowptr[i] = p;
        g_cursor_node[i] = p;
        if (i == NN - 1) g_rowptr[NN] = NE;
    }
}
__global__ void k_fill(const int* __restrict__ ei) {
    int i = blockIdx.x * blockDim.x + threadIdx.x;
    if (i < NE / 4) {
        int4 c = ((const int4*)(ei + NE))[i];
        int4 r = ((const int4*)ei)[i];
        g_csr[atomicAdd(&g_cursor_node[c.x], 1)] = r.x;
        g_csr[atomicAdd(&g_cursor_node[c.y], 1)] = r.y;
        g_csr[atomicAdd(&g_cursor_node[c.z], 1)] = r.z;
        g_csr[atomicAdd(&g_cursor_node[c.w], 1)] = r.w;
    }
}

// ---------------- fused gather + tf32 GEMM, layer 1 (K=64) ----------------
// smem: sXu [64][68] tf32 bits (17408 B). W read from global (B-fragments).
__global__ void __launch_bounds__(256) k_gcn1(
    const float* __restrict__ x, const float* __restrict__ W,
    const float* __restrict__ bias)
{
    constexpr int K = 64, KP = 68, BM = 64;
    __shared__ uint32_t sXu[BM * KP];

    int tid = threadIdx.x;
    int warp = tid >> 5, lane = tid & 31;
    int row0 = blockIdx.x * BM;

    // gather phase: 4 iterations of 2 nodes per warp (half-warp each)
    int half = lane >> 4, l = lane & 15;
    for (int it = 0; it < 4; it++) {
        int nl = warp * 8 + it * 2 + half;
        int node = row0 + nl;
        float4 acc = make_float4(0.f, 0.f, 0.f, 0.f);
        if (node < NN) {
            float dn = g_dinv[node];
            acc = *(const float4*)&x[node * INCH + l * 4];
            acc.x *= dn; acc.y *= dn; acc.z *= dn; acc.w *= dn;
            int e = g_rowptr[node], end = g_rowptr[node + 1];
            for (; e + 4 <= end; e += 4) {
                int s0 = g_csr[e], s1 = g_csr[e + 1], s2 = g_csr[e + 2], s3 = g_csr[e + 3];
                float4 a0 = *(const float4*)&x[s0 * INCH + l * 4];
                float4 a1 = *(const float4*)&x[s1 * INCH + l * 4];
                float4 a2 = *(const float4*)&x[s2 * INCH + l * 4];
                float4 a3 = *(const float4*)&x[s3 * INCH + l * 4];
                float d0 = g_dinv[s0], d1 = g_dinv[s1], d2 = g_dinv[s2], d3 = g_dinv[s3];
                acc.x = fmaf(d0, a0.x, fmaf(d1, a1.x, fmaf(d2, a2.x, fmaf(d3, a3.x, acc.x))));
                acc.y = fmaf(d0, a0.y, fmaf(d1, a1.y, fmaf(d2, a2.y, fmaf(d3, a3.y, acc.y))));
                acc.z = fmaf(d0, a0.z, fmaf(d1, a1.z, fmaf(d2, a2.z, fmaf(d3, a3.z, acc.z))));
                acc.w = fmaf(d0, a0.w, fmaf(d1, a1.w, fmaf(d2, a2.w, fmaf(d3, a3.w, acc.w))));
            }
            for (; e < end; e++) {
                int s = g_csr[e];
                float4 a = *(const float4*)&x[s * INCH + l * 4];
                float ds = g_dinv[s];
                acc.x = fmaf(ds, a.x, acc.x);
                acc.y = fmaf(ds, a.y, acc.y);
                acc.z = fmaf(ds, a.z, acc.z);
                acc.w = fmaf(ds, a.w, acc.w);
            }
            acc.x *= dn; acc.y *= dn; acc.z *= dn; acc.w *= dn;  // left norm
        }
        uint4 uv = make_uint4(cvt_tf32(acc.x), cvt_tf32(acc.y),
                              cvt_tf32(acc.z), cvt_tf32(acc.w));
        *(uint4*)&sXu[nl * KP + l * 4] = uv;
    }
    __syncthreads();

    // tf32 GEMM: warp = (mt = warp&3 -> rows mt*16.., nh = warp>>2 -> cols nh*64..)
    int mt = warp & 3, nh = warp >> 2;
    int ra = lane >> 2, ca = lane & 3;
    float d[8][4];
#pragma unroll
    for (int nt = 0; nt < 8; nt++)
        d[nt][0] = d[nt][1] = d[nt][2] = d[nt][3] = 0.f;

#pragma unroll
    for (int k0 = 0; k0 < K; k0 += 8) {
        const uint32_t* pa = &sXu[(mt * 16 + ra) * KP + k0 + ca];
        uint32_t A[4] = { pa[0], pa[8 * KP], pa[4], pa[8 * KP + 4] };
        const float* wb = &W[(k0 + ca) * 128 + nh * 64 + ra];
#pragma unroll
        for (int nt = 0; nt < 8; nt++) {
            uint32_t b0 = cvt_tf32(__ldg(wb + nt * 8));
            uint32_t b1 = cvt_tf32(__ldg(wb + 4 * 128 + nt * 8));
            mma_tf32(d[nt], A, b0, b1);
        }
    }

    // epilogue: bias + relu + dinv -> g_hws
    int gr0 = row0 + mt * 16 + ra;
    int gr1 = gr0 + 8;
    float dv0 = (gr0 < NN) ? g_dinv[gr0] : 0.f;
    float dv1 = (gr1 < NN) ? g_dinv[gr1] : 0.f;
#pragma unroll
    for (int nt = 0; nt < 8; nt++) {
        int col = nh * 64 + nt * 8 + 2 * ca;
        float bx = __ldg(&bias[col]), by = __ldg(&bias[col + 1]);
        if (gr0 < NN) {
            float2 o = make_float2(fmaxf(d[nt][0] + bx, 0.f) * dv0,
                                   fmaxf(d[nt][1] + by, 0.f) * dv0);
            *(float2*)&g_hws[gr0 * EMB + col] = o;
        }
        if (gr1 < NN) {
            float2 o = make_float2(fmaxf(d[nt][2] + bx, 0.f) * dv1,
                                   fmaxf(d[nt][3] + by, 0.f) * dv1);
            *(float2*)&g_hws[gr1 * EMB + col] = o;
        }
    }
}

// ---------------- fused gather + tf32 GEMM + pool, layer 2 (K=128) ----------------
// smem: sXu [64][132] tf32 bits (33792 B).
__global__ void __launch_bounds__(256) k_gcn2(
    const float* __restrict__ W, const float* __restrict__ bias,
    const int* __restrict__ batch)
{
    constexpr int K = 128, KP = 132, BM = 64;
    __shared__ uint32_t sXu[BM * KP];

    int tid = threadIdx.x;
    int warp = tid >> 5, lane = tid & 31;
    int row0 = blockIdx.x * BM;

    // gather phase: warp per node, 8 nodes per warp
    for (int it = 0; it < 8; it++) {
        int nl = warp * 8 + it;
        int node = row0 + nl;
        float4 acc = make_float4(0.f, 0.f, 0.f, 0.f);
        if (node < NN) {
            acc = *(const float4*)&g_hws[node * EMB + lane * 4];  // self
            int e = g_rowptr[node], end = g_rowptr[node + 1];
            for (; e + 4 <= end; e += 4) {
                int s0 = g_csr[e], s1 = g_csr[e + 1], s2 = g_csr[e + 2], s3 = g_csr[e + 3];
                float4 a0 = *(const float4*)&g_hws[s0 * EMB + lane * 4];
                float4 a1 = *(const float4*)&g_hws[s1 * EMB + lane * 4];
                float4 a2 = *(const float4*)&g_hws[s2 * EMB + lane * 4];
                float4 a3 = *(const float4*)&g_hws[s3 * EMB + lane * 4];
                acc = f4add(acc, f4add(f4add(a0, a1), f4add(a2, a3)));
            }
            for (; e < end; e++) {
                int s = g_csr[e];
                acc = f4add(acc, *(const float4*)&g_hws[s * EMB + lane * 4]);
            }
            float dn = g_dinv[node];
            acc.x *= dn; acc.y *= dn; acc.z *= dn; acc.w *= dn;
        }
        uint4 uv = make_uint4(cvt_tf32(acc.x), cvt_tf32(acc.y),
                              cvt_tf32(acc.z), cvt_tf32(acc.w));
        *(uint4*)&sXu[nl * KP + lane * 4] = uv;
    }
    __syncthreads();

    // tf32 GEMM
    int mt = warp & 3, nh = warp >> 2;
    int ra = lane >> 2, ca = lane & 3;
    float d[8][4];
#pragma unroll
    for (int nt = 0; nt < 8; nt++)
        d[nt][0] = d[nt][1] = d[nt][2] = d[nt][3] = 0.f;

#pragma unroll 4
    for (int k0 = 0; k0 < K; k0 += 8) {
        const uint32_t* pa = &sXu[(mt * 16 + ra) * KP + k0 + ca];
        uint32_t A[4] = { pa[0], pa[8 * KP], pa[4], pa[8 * KP + 4] };
        const float* wb = &W[(k0 + ca) * 128 + nh * 64 + ra];
#pragma unroll
        for (int nt = 0; nt < 8; nt++) {
            uint32_t b0 = cvt_tf32(__ldg(wb + nt * 8));
            uint32_t b1 = cvt_tf32(__ldg(wb + 4 * 128 + nt * 8));
            mma_tf32(d[nt], A, b0, b1);
        }
    }

    // epilogue: bias + relu + pooled red.add into g_gsum
    int gr0 = row0 + mt * 16 + ra;
    int gr1 = gr0 + 8;
    int b0i = (gr0 < NN) ? batch[gr0] : 0;
    int b1i = (gr1 < NN) ? batch[gr1] : 0;
#pragma unroll
    for (int nt = 0; nt < 8; nt++) {
        int col = nh * 64 + nt * 8 + 2 * ca;
        float bx = __ldg(&bias[col]), by = __ldg(&bias[col + 1]);
        if (gr0 < NN)
            red_add_v2(&g_gsum[b0i * EMB + col],
                       fmaxf(d[nt][0] + bx, 0.f), fmaxf(d[nt][1] + by, 0.f));
        if (gr1 < NN)
            red_add_v2(&g_gsum[b1i * EMB + col],
                       fmaxf(d[nt][2] + bx, 0.f), fmaxf(d[nt][3] + by, 0.f));
    }
}

// ---------------- mean epilogue ----------------
__global__ void __launch_bounds__(256) k_ge(const int* __restrict__ batch) {
    int w = (blockIdx.x * 256 + threadIdx.x) >> 5;
    int lane = threadIdx.x & 31;
    if (w >= NG) return;
    int cnt = 0;
    if (lane == 0) {
        int lo = 0, hi = NN;
        while (lo < hi) { int m = (lo + hi) >> 1; if (batch[m] < w) lo = m + 1; else hi = m; }
        int a = lo;
        hi = NN;
        while (lo < hi) { int m = (lo + hi) >> 1; if (batch[m] < w + 1) lo = m + 1; else hi = m; }
        cnt = lo - a;
    }
    cnt = __shfl_sync(0xffffffffu, cnt, 0);
    float inv = 1.0f / fmaxf((float)cnt, 1.0f);
    float4 v = *(const float4*)&g_gsum[w * EMB + lane * 4];
    v.x *= inv; v.y *= inv; v.z *= inv; v.w *= inv;
    *(float4*)&g_ge[w * EMB + lane * 4] = v;
}

// ---------------- fused bucketing ----------------
__global__ void __launch_bounds__(1024) k_bucket(const int* __restrict__ ecl) {
    __shared__ int s_cnt[NC];
    __shared__ int s_start[NC];
    __shared__ int s_cur[NC];
    int t = threadIdx.x;
    if (t < NC) s_cnt[t] = 0;
    __syncthreads();
    for (int p = t; p < NP; p += 1024) atomicAdd(&s_cnt[ecl[p]], 1);
    __syncthreads();
    if (t == 0) {
        int a = 0;
        for (int c = 0; c < NC; c++) {
            s_start[c] = a;
            a += ((s_cnt[c] + 31) / 32) * 32;
        }
    }
    __syncthreads();
    for (int i = t; i < BUCKET_SLOTS; i += 1024) g_bucket[i] = -1;
    if (t < NC) s_cur[t] = s_start[t];
    __syncthreads();
    for (int p = t; p < NP; p += 1024) {
        int c = ecl[p];
        int pos = atomicAdd(&s_cur[c], 1);
        g_bucket[pos] = p;
    }
}

// ---------------- tf32 tensor-core regressor: 32 pairs per block ----------------
__global__ void __launch_bounds__(256) k_reg(
    const int* __restrict__ ddb, const int* __restrict__ ecl,
    const float* __restrict__ w1, const float* __restrict__ b1,
    const float* __restrict__ w2, const float* __restrict__ b2,
    float* __restrict__ out)
{
    __shared__ int      s_pid[32];
    __shared__ uint32_t s_pairU[32 * 268];
    __shared__ float    s_b1[HID];
    __shared__ float    s_w2[HID];
    __shared__ float    s_out[32];

    int tid = threadIdx.x;
    int warp = tid >> 5, lane = tid & 31;
    int base = blockIdx.x * 32;
    if (tid < 32) { s_pid[tid] = g_bucket[base + tid]; s_out[tid] = 0.f; }
    __syncthreads();

    int c = -1;
    for (int s = 0; s < 32 && c < 0; s++) {
        int p = s_pid[s];
        if (p >= 0) c = ecl[p];
    }
    if (c < 0) return;

    s_b1[tid] = b1[c * HID + tid];
    s_w2[tid] = w2[c * HID + tid];

    for (int i = tid; i < 32 * HID; i += 256) {
        int s = i >> 8, j = i & 255;
        int p = s_pid[s];
        float v = 0.0f;
        if (p >= 0) {
            int q = (j < 128) ? ddb[p] : ddb[NP + p];
            v = g_ge[q * EMB + (j & 127)];
        }
        s_pairU[s * 268 + j] = cvt_tf32(v);
    }
    __syncthreads();

    const float* Wc = w1 + c * (HID * HID);
    int n0 = warp * 32;
    int ra = lane >> 2, ca = lane & 3;

    float d[2][4][4];
#pragma unroll
    for (int mt = 0; mt < 2; mt++)
#pragma unroll
        for (int nt = 0; nt < 4; nt++)
            d[mt][nt][0] = d[mt][nt][1] = d[mt][nt][2] = d[mt][nt][3] = 0.f;

    for (int k0 = 0; k0 < HID; k0 += 8) {
        const uint32_t* pr = &s_pairU[ra * 268 + k0 + ca];
        uint32_t A[2][4];
        A[0][0] = pr[0];
        A[0][1] = pr[8 * 268];
        A[0][2] = pr[4];
        A[0][3] = pr[8 * 268 + 4];
        A[1][0] = pr[16 * 268];
        A[1][1] = pr[24 * 268];
        A[1][2] = pr[16 * 268 + 4];
        A[1][3] = pr[24 * 268 + 4];
        const float* wp0 = Wc + (k0 + ca) * HID + n0 + ra;
        const float* wp1 = wp0 + 4 * HID;
#pragma unroll
        for (int nt = 0; nt < 4; nt++) {
            uint32_t b0 = cvt_tf32(__ldg(wp0 + nt * 8));
            uint32_t b1v = cvt_tf32(__ldg(wp1 + nt * 8));
            mma_tf32(d[0][nt], A[0], b0, b1v);
            mma_tf32(d[1][nt], A[1], b0, b1v);
        }
    }

    float rowsum[2][2] = {{0.f, 0.f}, {0.f, 0.f}};
#pragma unroll
    for (int mt = 0; mt < 2; mt++) {
#pragma unroll
        for (int nt = 0; nt < 4; nt++) {
            int colb = n0 + nt * 8 + 2 * ca;
            float b1a = s_b1[colb],     w2a = s_w2[colb];
            float b1b = s_b1[colb + 1], w2b = s_w2[colb + 1];
            rowsum[mt][0] += fmaxf(d[mt][nt][0] + b1a, 0.f) * w2a
                           + fmaxf(d[mt][nt][1] + b1b, 0.f) * w2b;
            rowsum[mt][1] += fmaxf(d[mt][nt][2] + b1a, 0.f) * w2a
                           + fmaxf(d[mt][nt][3] + b1b, 0.f) * w2b;
        }
    }
#pragma unroll
    for (int mt = 0; mt < 2; mt++)
#pragma unroll
        for (int hi = 0; hi < 2; hi++) {
            float v = rowsum[mt][hi];
            v += __shfl_xor_sync(0xffffffffu, v, 1);
            v += __shfl_xor_sync(0xffffffffu, v, 2);
            if (ca == 0) atomicAdd(&s_out[mt * 16 + hi * 8 + ra], v);
        }
    __syncthreads();

    if (tid < 32) {
        int p = s_pid[tid];
        if (p >= 0) out[p] = s_out[tid] + b2[c];
    }
}

// ---------------- host launch ----------------
extern "C" void kernel_launch(void* const* d_in, const int* in_sizes, int n_in,
                              void* d_out, int out_size)
{
    const float* x    = (const float*)d_in[0];
    const float* c1w  = (const float*)d_in[1];
    const float* c1b  = (const float*)d_in[2];
    const float* c2w  = (const float*)d_in[3];
    const float* c2b  = (const float*)d_in[4];
    const float* rw1  = (const float*)d_in[5];
    const float* rb1  = (const float*)d_in[6];
    const float* rw2  = (const float*)d_in[7];
    const float* rb2  = (const float*)d_in[8];
    const int*   ei   = (const int*)d_in[9];
    const int*   bat  = (const int*)d_in[10];
    const int*   ddb  = (const int*)d_in[11];
    const int*   ecl  = (const int*)d_in[12];
    float* out = (float*)d_out;

    void* icnt_ptr = nullptr;
    void* gsum_ptr = nullptr;
    cudaGetSymbolAddress(&icnt_ptr, g_icnt);
    cudaGetSymbolAddress(&gsum_ptr, g_gsum);

    const int T = 256;

    cudaMemsetAsync(icnt_ptr, 0, NN * sizeof(int), 0);
    cudaMemsetAsync(gsum_ptr, 0, NG * EMB * sizeof(float), 0);

    // degree histogram + dinv + CSR build
    k_icnt<<<(NE / 4 + T - 1) / T, T>>>(ei);
    k_scan1<<<NBLK, NPB>>>();
    k_scan2<<<1, 512>>>();
    k_scan3<<<NBLK, NPB>>>();
    k_fill<<<(NE / 4 + T - 1) / T, T>>>(ei);

    // layer 1: fused gather(64) + tf32 GEMM
    k_gcn1<<<(NN + 63) / 64, T>>>(x, c1w, c1b);

    // layer 2: fused gather(128) + tf32 GEMM + pooling
    k_gcn2<<<(NN + 63) / 64, T>>>(c2w, c2b, bat);
    k_ge<<<(NG * 32 + T - 1) / T, T>>>(bat);

    // bucketing + regressor (tf32 tensor cores)
    k_bucket<<<1, 1024>>>(ecl);
    k_reg<<<REG_BLOCKS, T>>>(ddb, ecl, rw1, rb1, rw2, rb2, out);
}

// round 9
// speedup vs baseline: 1.4080x; 1.0088x over previous
#include <cuda_runtime.h>
#include <cuda_fp16.h>
#include <math.h>
#include <stdint.h>

#define NN 50000
#define NE 800000
#define NG 1024
#define NP 16384
#define NC 16
#define INCH 64
#define EMB 128
#define HID 256
#define BUCKET_SLOTS ((NP / 32 + NC) * 32)   // 16896
#define REG_BLOCKS (NP / 32 + NC)            // 528
#define NPB 128
#define NBLK ((NN + NPB - 1) / NPB)           // 391

// ---------------- scratch ----------------
__device__ float  g_dinv[NN];
__device__ int    g_icnt[NN];
__device__ int    g_rowptr[NN + 1];
__device__ int    g_cursor_node[NN];
__device__ int    g_bsum[512];
__device__ int    g_csr[NE];
__device__ __half g_xh[NN * INCH];       // fp16 copy of x
__device__ __half g_hws[NN * EMB];       // fp16 dinv*relu(h1)
__device__ float  g_gsum[NG * EMB];
__device__ float  g_ge[NG * EMB];
__device__ int    g_bucket[BUCKET_SLOTS];

// ---------------- helpers ----------------
__device__ __forceinline__ void red_add_v2(float* addr, float a, float b) {
    asm volatile("red.global.add.v2.f32 [%0], {%1, %2};"
                 :: "l"(addr), "f"(a), "f"(b) : "memory");
}
__device__ __forceinline__ float4 f4add(float4 a, float4 b) {
    return make_float4(a.x + b.x, a.y + b.y, a.z + b.z, a.w + b.w);
}
__device__ __forceinline__ uint32_t cvt_tf32(float f) {
    uint32_t u;
    asm("cvt.rna.tf32.f32 %0, %1;" : "=r"(u) : "f"(f));
    return u;
}
__device__ __forceinline__ void mma_tf32(float* d, const uint32_t* a,
                                         uint32_t b0, uint32_t b1) {
    asm("mma.sync.aligned.m16n8k8.row.col.f32.tf32.tf32.f32 "
        "{%0,%1,%2,%3}, {%4,%5,%6,%7}, {%8,%9}, {%0,%1,%2,%3};"
        : "+f"(d[0]), "+f"(d[1]), "+f"(d[2]), "+f"(d[3])
        : "r"(a[0]), "r"(a[1]), "r"(a[2]), "r"(a[3]), "r"(b0), "r"(b1));
}
// load 4 consecutive halves as float4 (8-byte load)
__device__ __forceinline__ float4 ldh4(const __half* p) {
    uint2 u = *(const uint2*)p;
    __half2 h0 = *(__half2*)&u.x, h1 = *(__half2*)&u.y;
    float2 f0 = __half22float2(h0), f1 = __half22float2(h1);
    return make_float4(f0.x, f0.y, f1.x, f1.y);
}

// ---------------- x -> fp16 ----------------
__global__ void k_tohalf(const float* __restrict__ x) {
    int i = blockIdx.x * blockDim.x + threadIdx.x;
    if (i < NN * INCH / 4) {
        float4 v = ((const float4*)x)[i];
        __half2 h0 = __floats2half2_rn(v.x, v.y);
        __half2 h1 = __floats2half2_rn(v.z, v.w);
        uint2 u = make_uint2(*(uint32_t*)&h0, *(uint32_t*)&h1);
        ((uint2*)g_xh)[i] = u;
    }
}

// ---------------- degree histogram (4 edges per thread) ----------------
__global__ void k_icnt(const int* __restrict__ ei) {
    int i = blockIdx.x * blockDim.x + threadIdx.x;
    if (i < NE / 4) {
        int4 t = ((const int4*)(ei + NE))[i];
        atomicAdd(&g_icnt[t.x], 1);
        atomicAdd(&g_icnt[t.y], 1);
        atomicAdd(&g_icnt[t.z], 1);
        atomicAdd(&g_icnt[t.w], 1);
    }
}

// ---------------- prefix scan (+ fused dinv) ----------------
__global__ void k_scan1() {
    __shared__ int sm[NPB];
    int i = blockIdx.x * NPB + threadIdx.x;
    int v = (i < NN) ? g_icnt[i] : 0;
    if (i < NN) g_dinv[i] = rsqrtf((float)(v + 1));
    sm[threadIdx.x] = v;
    __syncthreads();
    for (int s = NPB / 2; s > 0; s >>= 1) {
        if (threadIdx.x < s) sm[threadIdx.x] += sm[threadIdx.x + s];
        __syncthreads();
    }
    if (threadIdx.x == 0) g_bsum[blockIdx.x] = sm[0];
}
__global__ void k_scan2() {
    __shared__ int sm[512];
    int t = threadIdx.x;
    int v = (t < NBLK) ? g_bsum[t] : 0;
    sm[t] = v;
    __syncthreads();
    for (int s = 1; s < 512; s <<= 1) {
        int a = (t >= s) ? sm[t - s] : 0;
        __syncthreads();
        sm[t] += a;
        __syncthreads();
    }
    if (t < NBLK) g_bsum[t] = sm[t] - v;
}
__global__ void k_scan3() {
    __shared__ int sm[NPB];
    int t = threadIdx.x;
    int i = blockIdx.x * NPB + t;
    int v = (i < NN) ? g_icnt[i] : 0;
    sm[t] = v;
    __syncthreads();
    for (int s = 1; s < NPB; s <<= 1) {
        int a = (t >= s) ? sm[t - s] : 0;
        __syncthreads();
        sm[t] += a;
        __syncthreads();
    }
    if (i < NN) {
        int p = g_bsum[blockIdx.x] + sm[t] - v;
        g_rowptr[i] = p;
        g_cursor_node[i] = p;
        if (i == NN - 1) g_rowptr[NN] = NE;
    }
}
__global__ void k_fill(const int* __restrict__ ei) {
    int i = blockIdx.x * blockDim.x + threadIdx.x;
    if (i < NE / 4) {
        int4 c = ((const int4*)(ei + NE))[i];
        int4 r = ((const int4*)ei)[i];
        g_csr[atomicAdd(&g_cursor_node[c.x], 1)] = r.x;
        g_csr[atomicAdd(&g_cursor_node[c.y], 1)] = r.y;
        g_csr[atomicAdd(&g_cursor_node[c.z], 1)] = r.z;
        g_csr[atomicAdd(&g_cursor_node[c.w], 1)] = r.w;
    }
}

// ---------------- fused gather(fp16) + tf32 GEMM, layer 1 (K=64) ----------------
__global__ void __launch_bounds__(256) k_gcn1(
    const float* __restrict__ W, const float* __restrict__ bias)
{
    constexpr int K = 64, KP = 68, BM = 64;
    __shared__ uint32_t sXu[BM * KP];

    int tid = threadIdx.x;
    int warp = tid >> 5, lane = tid & 31;
    int row0 = blockIdx.x * BM;

    // gather phase: half-warp per node (16 lanes x 4 halves = 64 cols)
    int half = lane >> 4, l = lane & 15;
    for (int it = 0; it < 4; it++) {
        int nl = warp * 8 + it * 2 + half;
        int node = row0 + nl;
        float4 acc = make_float4(0.f, 0.f, 0.f, 0.f);
        if (node < NN) {
            float dn = g_dinv[node];
            acc = ldh4(&g_xh[node * INCH + l * 4]);
            acc.x *= dn; acc.y *= dn; acc.z *= dn; acc.w *= dn;
            int e = g_rowptr[node], end = g_rowptr[node + 1];
            for (; e + 4 <= end; e += 4) {
                int s0 = g_csr[e], s1 = g_csr[e + 1], s2 = g_csr[e + 2], s3 = g_csr[e + 3];
                float4 a0 = ldh4(&g_xh[s0 * INCH + l * 4]);
                float4 a1 = ldh4(&g_xh[s1 * INCH + l * 4]);
                float4 a2 = ldh4(&g_xh[s2 * INCH + l * 4]);
                float4 a3 = ldh4(&g_xh[s3 * INCH + l * 4]);
                float d0 = g_dinv[s0], d1 = g_dinv[s1], d2 = g_dinv[s2], d3 = g_dinv[s3];
                acc.x = fmaf(d0, a0.x, fmaf(d1, a1.x, fmaf(d2, a2.x, fmaf(d3, a3.x, acc.x))));
                acc.y = fmaf(d0, a0.y, fmaf(d1, a1.y, fmaf(d2, a2.y, fmaf(d3, a3.y, acc.y))));
                acc.z = fmaf(d0, a0.z, fmaf(d1, a1.z, fmaf(d2, a2.z, fmaf(d3, a3.z, acc.z))));
                acc.w = fmaf(d0, a0.w, fmaf(d1, a1.w, fmaf(d2, a2.w, fmaf(d3, a3.w, acc.w))));
            }
            for (; e < end; e++) {
                int s = g_csr[e];
                float4 a = ldh4(&g_xh[s * INCH + l * 4]);
                float ds = g_dinv[s];
                acc.x = fmaf(ds, a.x, acc.x);
                acc.y = fmaf(ds, a.y, acc.y);
                acc.z = fmaf(ds, a.z, acc.z);
                acc.w = fmaf(ds, a.w, acc.w);
            }
            acc.x *= dn; acc.y *= dn; acc.z *= dn; acc.w *= dn;  // left norm
        }
        uint4 uv = make_uint4(cvt_tf32(acc.x), cvt_tf32(acc.y),
                              cvt_tf32(acc.z), cvt_tf32(acc.w));
        *(uint4*)&sXu[nl * KP + l * 4] = uv;
    }
    __syncthreads();

    // tf32 GEMM
    int mt = warp & 3, nh = warp >> 2;
    int ra = lane >> 2, ca = lane & 3;
    float d[8][4];
#pragma unroll
    for (int nt = 0; nt < 8; nt++)
        d[nt][0] = d[nt][1] = d[nt][2] = d[nt][3] = 0.f;

#pragma unroll
    for (int k0 = 0; k0 < K; k0 += 8) {
        const uint32_t* pa = &sXu[(mt * 16 + ra) * KP + k0 + ca];
        uint32_t A[4] = { pa[0], pa[8 * KP], pa[4], pa[8 * KP + 4] };
        const float* wb = &W[(k0 + ca) * 128 + nh * 64 + ra];
#pragma unroll
        for (int nt = 0; nt < 8; nt++) {
            uint32_t b0 = cvt_tf32(__ldg(wb + nt * 8));
            uint32_t b1 = cvt_tf32(__ldg(wb + 4 * 128 + nt * 8));
            mma_tf32(d[nt], A, b0, b1);
        }
    }

    // epilogue: bias + relu + dinv -> g_hws (fp16)
    int gr0 = row0 + mt * 16 + ra;
    int gr1 = gr0 + 8;
    float dv0 = (gr0 < NN) ? g_dinv[gr0] : 0.f;
    float dv1 = (gr1 < NN) ? g_dinv[gr1] : 0.f;
#pragma unroll
    for (int nt = 0; nt < 8; nt++) {
        int col = nh * 64 + nt * 8 + 2 * ca;
        float bx = __ldg(&bias[col]), by = __ldg(&bias[col + 1]);
        if (gr0 < NN) {
            __half2 o = __floats2half2_rn(fmaxf(d[nt][0] + bx, 0.f) * dv0,
                                          fmaxf(d[nt][1] + by, 0.f) * dv0);
            *(__half2*)&g_hws[gr0 * EMB + col] = o;
        }
        if (gr1 < NN) {
            __half2 o = __floats2half2_rn(fmaxf(d[nt][2] + bx, 0.f) * dv1,
                                          fmaxf(d[nt][3] + by, 0.f) * dv1);
            *(__half2*)&g_hws[gr1 * EMB + col] = o;
        }
    }
}

// ---------------- fused gather(fp16) + tf32 GEMM + pool, layer 2 (K=128) ----------------
__global__ void __launch_bounds__(256) k_gcn2(
    const float* __restrict__ W, const float* __restrict__ bias,
    const int* __restrict__ batch)
{
    constexpr int K = 128, KP = 132, BM = 64;
    __shared__ uint32_t sXu[BM * KP];

    int tid = threadIdx.x;
    int warp = tid >> 5, lane = tid & 31;
    int row0 = blockIdx.x * BM;

    // gather phase: warp per node, lane handles 4 halves (8B loads)
    for (int it = 0; it < 8; it++) {
        int nl = warp * 8 + it;
        int node = row0 + nl;
        float4 acc = make_float4(0.f, 0.f, 0.f, 0.f);
        if (node < NN) {
            acc = ldh4(&g_hws[node * EMB + lane * 4]);  // self
            int e = g_rowptr[node], end = g_rowptr[node + 1];
            for (; e + 4 <= end; e += 4) {
                int s0 = g_csr[e], s1 = g_csr[e + 1], s2 = g_csr[e + 2], s3 = g_csr[e + 3];
                float4 a0 = ldh4(&g_hws[s0 * EMB + lane * 4]);
                float4 a1 = ldh4(&g_hws[s1 * EMB + lane * 4]);
                float4 a2 = ldh4(&g_hws[s2 * EMB + lane * 4]);
                float4 a3 = ldh4(&g_hws[s3 * EMB + lane * 4]);
                acc = f4add(acc, f4add(f4add(a0, a1), f4add(a2, a3)));
            }
            for (; e < end; e++) {
                int s = g_csr[e];
                acc = f4add(acc, ldh4(&g_hws[s * EMB + lane * 4]));
            }
            float dn = g_dinv[node];
            acc.x *= dn; acc.y *= dn; acc.z *= dn; acc.w *= dn;
        }
        uint4 uv = make_uint4(cvt_tf32(acc.x), cvt_tf32(acc.y),
                              cvt_tf32(acc.z), cvt_tf32(acc.w));
        *(uint4*)&sXu[nl * KP + lane * 4] = uv;
    }
    __syncthreads();

    // tf32 GEMM
    int mt = warp & 3, nh = warp >> 2;
    int ra = lane >> 2, ca = lane & 3;
    float d[8][4];
#pragma unroll
    for (int nt = 0; nt < 8; nt++)
        d[nt][0] = d[nt][1] = d[nt][2] = d[nt][3] = 0.f;

#pragma unroll 4
    for (int k0 = 0; k0 < K; k0 += 8) {
        const uint32_t* pa = &sXu[(mt * 16 + ra) * KP + k0 + ca];
        uint32_t A[4] = { pa[0], pa[8 * KP], pa[4], pa[8 * KP + 4] };
        const float* wb = &W[(k0 + ca) * 128 + nh * 64 + ra];
#pragma unroll
        for (int nt = 0; nt < 8; nt++) {
            uint32_t b0 = cvt_tf32(__ldg(wb + nt * 8));
            uint32_t b1 = cvt_tf32(__ldg(wb + 4 * 128 + nt * 8));
            mma_tf32(d[nt], A, b0, b1);
        }
    }

    // epilogue: bias + relu + pooled red.add into g_gsum
    int gr0 = row0 + mt * 16 + ra;
    int gr1 = gr0 + 8;
    int b0i = (gr0 < NN) ? batch[gr0] : 0;
    int b1i = (gr1 < NN) ? batch[gr1] : 0;
#pragma unroll
    for (int nt = 0; nt < 8; nt++) {
        int col = nh * 64 + nt * 8 + 2 * ca;
        float bx = __ldg(&bias[col]), by = __ldg(&bias[col + 1]);
        if (gr0 < NN)
            red_add_v2(&g_gsum[b0i * EMB + col],
                       fmaxf(d[nt][0] + bx, 0.f), fmaxf(d[nt][1] + by, 0.f));
        if (gr1 < NN)
            red_add_v2(&g_gsum[b1i * EMB + col],
                       fmaxf(d[nt][2] + bx, 0.f), fmaxf(d[nt][3] + by, 0.f));
    }
}

// ---------------- mean epilogue ----------------
__global__ void __launch_bounds__(256) k_ge(const int* __restrict__ batch) {
    int w = (blockIdx.x * 256 + threadIdx.x) >> 5;
    int lane = threadIdx.x & 31;
    if (w >= NG) return;
    int cnt = 0;
    if (lane == 0) {
        int lo = 0, hi = NN;
        while (lo < hi) { int m = (lo + hi) >> 1; if (batch[m] < w) lo = m + 1; else hi = m; }
        int a = lo;
        hi = NN;
        while (lo < hi) { int m = (lo + hi) >> 1; if (batch[m] < w + 1) lo = m + 1; else hi = m; }
        cnt = lo - a;
    }
    cnt = __shfl_sync(0xffffffffu, cnt, 0);
    float inv = 1.0f / fmaxf((float)cnt, 1.0f);
    float4 v = *(const float4*)&g_gsum[w * EMB + lane * 4];
    v.x *= inv; v.y *= inv; v.z *= inv; v.w *= inv;
    *(float4*)&g_ge[w * EMB + lane * 4] = v;
}

// ---------------- fused bucketing ----------------
__global__ void __launch_bounds__(1024) k_bucket(const int* __restrict__ ecl) {
    __shared__ int s_cnt[NC];
    __shared__ int s_start[NC];
    __shared__ int s_cur[NC];
    int t = threadIdx.x;
    if (t < NC) s_cnt[t] = 0;
    __syncthreads();
    for (int p = t; p < NP; p += 1024) atomicAdd(&s_cnt[ecl[p]], 1);
    __syncthreads();
    if (t == 0) {
        int a = 0;
        for (int c = 0; c < NC; c++) {
            s_start[c] = a;
            a += ((s_cnt[c] + 31) / 32) * 32;
        }
    }
    __syncthreads();
    for (int i = t; i < BUCKET_SLOTS; i += 1024) g_bucket[i] = -1;
    if (t < NC) s_cur[t] = s_start[t];
    __syncthreads();
    for (int p = t; p < NP; p += 1024) {
        int c = ecl[p];
        int pos = atomicAdd(&s_cur[c], 1);
        g_bucket[pos] = p;
    }
}

// ---------------- tf32 tensor-core regressor: 32 pairs per block ----------------
__global__ void __launch_bounds__(256) k_reg(
    const int* __restrict__ ddb, const int* __restrict__ ecl,
    const float* __restrict__ w1, const float* __restrict__ b1,
    const float* __restrict__ w2, const float* __restrict__ b2,
    float* __restrict__ out)
{
    __shared__ int      s_pid[32];
    __shared__ uint32_t s_pairU[32 * 268];
    __shared__ float    s_b1[HID];
    __shared__ float    s_w2[HID];
    __shared__ float    s_out[32];

    int tid = threadIdx.x;
    int warp = tid >> 5, lane = tid & 31;
    int base = blockIdx.x * 32;
    if (tid < 32) { s_pid[tid] = g_bucket[base + tid]; s_out[tid] = 0.f; }
    __syncthreads();

    int c = -1;
    for (int s = 0; s < 32 && c < 0; s++) {
        int p = s_pid[s];
        if (p >= 0) c = ecl[p];
    }
    if (c < 0) return;

    s_b1[tid] = b1[c * HID + tid];
    s_w2[tid] = w2[c * HID + tid];

    for (int i = tid; i < 32 * HID; i += 256) {
        int s = i >> 8, j = i & 255;
        int p = s_pid[s];
        float v = 0.0f;
        if (p >= 0) {
            int q = (j < 128) ? ddb[p] : ddb[NP + p];
            v = g_ge[q * EMB + (j & 127)];
        }
        s_pairU[s * 268 + j] = cvt_tf32(v);
    }
    __syncthreads();

    const float* Wc = w1 + c * (HID * HID);
    int n0 = warp * 32;
    int ra = lane >> 2, ca = lane & 3;

    float d[2][4][4];
#pragma unroll
    for (int mt = 0; mt < 2; mt++)
#pragma unroll
        for (int nt = 0; nt < 4; nt++)
            d[mt][nt][0] = d[mt][nt][1] = d[mt][nt][2] = d[mt][nt][3] = 0.f;

    for (int k0 = 0; k0 < HID; k0 += 8) {
        const uint32_t* pr = &s_pairU[ra * 268 + k0 + ca];
        uint32_t A[2][4];
        A[0][0] = pr[0];
        A[0][1] = pr[8 * 268];
        A[0][2] = pr[4];
        A[0][3] = pr[8 * 268 + 4];
        A[1][0] = pr[16 * 268];
        A[1][1] = pr[24 * 268];
        A[1][2] = pr[16 * 268 + 4];
        A[1][3] = pr[24 * 268 + 4];
        const float* wp0 = Wc + (k0 + ca) * HID + n0 + ra;
        const float* wp1 = wp0 + 4 * HID;
#pragma unroll
        for (int nt = 0; nt < 4; nt++) {
            uint32_t b0 = cvt_tf32(__ldg(wp0 + nt * 8));
            uint32_t b1v = cvt_tf32(__ldg(wp1 + nt * 8));
            mma_tf32(d[0][nt], A[0], b0, b1v);
            mma_tf32(d[1][nt], A[1], b0, b1v);
        }
    }

    float rowsum[2][2] = {{0.f, 0.f}, {0.f, 0.f}};
#pragma unroll
    for (int mt = 0; mt < 2; mt++) {
#pragma unroll
        for (int nt = 0; nt < 4; nt++) {
            int colb = n0 + nt * 8 + 2 * ca;
            float b1a = s_b1[colb],     w2a = s_w2[colb];
            float b1b = s_b1[colb + 1], w2b = s_w2[colb + 1];
            rowsum[mt][0] += fmaxf(d[mt][nt][0] + b1a, 0.f) * w2a
                           + fmaxf(d[mt][nt][1] + b1b, 0.f) * w2b;
            rowsum[mt][1] += fmaxf(d[mt][nt][2] + b1a, 0.f) * w2a
                           + fmaxf(d[mt][nt][3] + b1b, 0.f) * w2b;
        }
    }
#pragma unroll
    for (int mt = 0; mt < 2; mt++)
#pragma unroll
        for (int hi = 0; hi < 2; hi++) {
            float v = rowsum[mt][hi];
            v += __shfl_xor_sync(0xffffffffu, v, 1);
            v += __shfl_xor_sync(0xffffffffu, v, 2);
            if (ca == 0) atomicAdd(&s_out[mt * 16 + hi * 8 + ra], v);
        }
    __syncthreads();

    if (tid < 32) {
        int p = s_pid[tid];
        if (p >= 0) out[p] = s_out[tid] + b2[c];
    }
}

// ---------------- host launch ----------------
extern "C" void kernel_launch(void* const* d_in, const int* in_sizes, int n_in,
                              void* d_out, int out_size)
{
    const float* x    = (const float*)d_in[0];
    const float* c1w  = (const float*)d_in[1];
    const float* c1b  = (const float*)d_in[2];
    const float* c2w  = (const float*)d_in[3];
    const float* c2b  = (const float*)d_in[4];
    const float* rw1  = (const float*)d_in[5];
    const float* rb1  = (const float*)d_in[6];
    const float* rw2  = (const float*)d_in[7];
    const float* rb2  = (const float*)d_in[8];
    const int*   ei   = (const int*)d_in[9];
    const int*   bat  = (const int*)d_in[10];
    const int*   ddb  = (const int*)d_in[11];
    const int*   ecl  = (const int*)d_in[12];
    float* out = (float*)d_out;

    void* icnt_ptr = nullptr;
    void* gsum_ptr = nullptr;
    cudaGetSymbolAddress(&icnt_ptr, g_icnt);
    cudaGetSymbolAddress(&gsum_ptr, g_gsum);

    const int T = 256;

    cudaMemsetAsync(icnt_ptr, 0, NN * sizeof(int), 0);
    cudaMemsetAsync(gsum_ptr, 0, NG * EMB * sizeof(float), 0);

    // x -> fp16 (independent of CSR chain)
    k_tohalf<<<(NN * INCH / 4 + T - 1) / T, T>>>(x);

    // degree histogram + dinv + CSR build
    k_icnt<<<(NE / 4 + T - 1) / T, T>>>(ei);
    k_scan1<<<NBLK, NPB>>>();
    k_scan2<<<1, 512>>>();
    k_scan3<<<NBLK, NPB>>>();
    k_fill<<<(NE / 4 + T - 1) / T, T>>>(ei);

    // layer 1: fused gather(fp16) + tf32 GEMM
    k_gcn1<<<(NN + 63) / 64, T>>>(c1w, c1b);

    // layer 2: fused gather(fp16) + tf32 GEMM + pooling
    k_gcn2<<<(NN + 63) / 64, T>>>(c2w, c2b, bat);
    k_ge<<<(NG * 32 + T - 1) / T, T>>>(bat);

    // bucketing + regressor (tf32 tensor cores)
    k_bucket<<<1, 1024>>>(ecl);
    k_reg<<<REG_BLOCKS, T>>>(ddb, ecl, rw1, rb1, rw2, rb2, out);
}